// round 15
// baseline (speedup 1.0000x reference)
#include <cuda_runtime.h>
#include <cuda_bf16.h>
#include <cuda_fp16.h>

// Problem constants (fixed by the dataset)
#define NNODES   100000
#define FIN      512
#define FHID     128
#define FOUT     40
#define NEDGES   3200000

#define SB 256           // scan block size
#define MAXSB 1024       // max scan blocks

// Scratch (device globals; no runtime allocation allowed)
__device__ __align__(256) __half g_support1h[(size_t)NNODES * FHID];  // fp16 gather table
__device__ __align__(256) __half g_agg1h[(size_t)NNODES * FHID];      // fp16 agg1
__device__ __align__(256) __half g_support2h[(size_t)NNODES * FOUT];  // fp16 layer-2 table
__device__ __align__(256) __nv_bfloat16 g_xhi[(size_t)NNODES * FIN];
__device__ __align__(256) __nv_bfloat16 g_xlo[(size_t)NNODES * FIN];
__device__ __align__(256) __nv_bfloat16 g_w1thi[FHID * FIN];   // transposed [n][k]
__device__ __align__(256) __nv_bfloat16 g_w1tlo[FHID * FIN];
__device__ __align__(256) int   g_src[NEDGES];
__device__ __align__(256) int   g_dst[NEDGES];
__device__ __align__(256) int   g_deg[NNODES];
__device__ __align__(256) int   g_off[NNODES + 1];
__device__ __align__(256) int   g_cursor[NNODES];
__device__ __align__(256) int2  g_csr[NEDGES];       // {src, w_bits}
__device__ __align__(256) int   g_bsum[MAXSB];
__device__ __align__(256) int   g_bbase[MAXSB];
__device__ int g_is64;

// ---------------------------------------------------------------------------
// Edge-index dtype detection (int64 vs int32), parallel
// ---------------------------------------------------------------------------
__global__ void detect_kernel(const void* ei, int E, int M) {
    const long long* p64 = (const long long*)ei;
    int step = E / 4096;
    int bad = 0;
#pragma unroll
    for (int j = 0; j < 16; j++) {
        int k = threadIdx.x * 16 + j;
        long long v = p64[(long long)k * step];
        if (v < 0 || v >= M) bad = 1;
    }
    bad = __syncthreads_or(bad);
    if (threadIdx.x == 0) g_is64 = !bad;
}

// ---------------------------------------------------------------------------
// Split precompute: x -> hi/lo bf16 planes; W1 -> transposed hi/lo planes
// ---------------------------------------------------------------------------
__global__ void split_x_kernel(const float* __restrict__ x, int M) {
    size_t i = (size_t)blockIdx.x * blockDim.x + threadIdx.x;   // float4 index
    size_t n4 = (size_t)M * (FIN / 4);
    if (i >= n4) return;
    float4 v = ((const float4*)x)[i];
    __nv_bfloat16 h0 = __float2bfloat16_rn(v.x);
    __nv_bfloat16 h1 = __float2bfloat16_rn(v.y);
    __nv_bfloat16 h2 = __float2bfloat16_rn(v.z);
    __nv_bfloat16 h3 = __float2bfloat16_rn(v.w);
    __nv_bfloat16 l0 = __float2bfloat16_rn(v.x - __bfloat162float(h0));
    __nv_bfloat16 l1 = __float2bfloat16_rn(v.y - __bfloat162float(h1));
    __nv_bfloat16 l2 = __float2bfloat16_rn(v.z - __bfloat162float(h2));
    __nv_bfloat16 l3 = __float2bfloat16_rn(v.w - __bfloat162float(h3));
    __nv_bfloat162 hp0; hp0.x = h0; hp0.y = h1;
    __nv_bfloat162 hp1; hp1.x = h2; hp1.y = h3;
    __nv_bfloat162 lp0; lp0.x = l0; lp0.y = l1;
    __nv_bfloat162 lp1; lp1.x = l2; lp1.y = l3;
    uint2 hv = make_uint2(*(unsigned*)&hp0, *(unsigned*)&hp1);
    uint2 lv = make_uint2(*(unsigned*)&lp0, *(unsigned*)&lp1);
    ((uint2*)g_xhi)[i] = hv;
    ((uint2*)g_xlo)[i] = lv;
}

__global__ void split_w1_kernel(const float* __restrict__ W1) {
    int i = blockIdx.x * blockDim.x + threadIdx.x;    // k*FHID + n
    if (i >= FIN * FHID) return;
    int k = i / FHID;
    int n = i % FHID;
    float v = W1[i];
    __nv_bfloat16 h = __float2bfloat16_rn(v);
    __nv_bfloat16 l = __float2bfloat16_rn(v - __bfloat162float(h));
    g_w1thi[n * FIN + k] = h;
    g_w1tlo[n * FIN + k] = l;
}

__global__ void zero_deg_kernel(int M) {
    int i = blockIdx.x * blockDim.x + threadIdx.x;
    if (i < M) g_deg[i] = 0;
}

__global__ void decode_hist_kernel(const void* ei, int E, int M) {
    int e = blockIdx.x * blockDim.x + threadIdx.x;
    if (e >= E) return;
    int s, d;
    if (g_is64) {
        const long long* p = (const long long*)ei;
        s = (int)p[e];
        d = (int)p[(size_t)E + e];
    } else {
        const int* p = (const int*)ei;
        s = p[e];
        d = p[(size_t)E + e];
    }
    s = min(max(s, 0), M - 1);
    d = min(max(d, 0), M - 1);
    g_src[e] = s;
    g_dst[e] = d;
    atomicAdd(&g_deg[d], 1);
}

// ---- 3-phase multi-block exclusive scan ----------------------------------
__global__ void scan1_kernel(int M) {
    __shared__ int sh[SB];
    int t = threadIdx.x;
    int i = blockIdx.x * SB + t;
    sh[t] = (i < M) ? g_deg[i] : 0;
    __syncthreads();
#pragma unroll
    for (int o = SB / 2; o > 0; o >>= 1) {
        if (t < o) sh[t] += sh[t + o];
        __syncthreads();
    }
    if (t == 0) g_bsum[blockIdx.x] = sh[0];
}

__global__ __launch_bounds__(MAXSB) void scan2_kernel(int nb, int E, int M) {
    __shared__ int sh[MAXSB];
    int t = threadIdx.x;
    sh[t] = (t < nb) ? g_bsum[t] : 0;
    __syncthreads();
#pragma unroll
    for (int o = 1; o < MAXSB; o <<= 1) {
        int u = (t >= o) ? sh[t - o] : 0;
        __syncthreads();
        sh[t] += u;
        __syncthreads();
    }
    if (t < nb) g_bbase[t] = (t > 0) ? sh[t - 1] : 0;
    if (t == 0) g_off[M] = E;
}

__global__ void scan3_kernel(int M) {
    __shared__ int sh[SB];
    int t = threadIdx.x;
    int i = blockIdx.x * SB + t;
    int v = (i < M) ? g_deg[i] : 0;
    sh[t] = v;
    __syncthreads();
#pragma unroll
    for (int o = 1; o < SB; o <<= 1) {
        int u = (t >= o) ? sh[t - o] : 0;
        __syncthreads();
        sh[t] += u;
        __syncthreads();
    }
    if (i < M) {
        int excl = sh[t] - v + g_bbase[blockIdx.x];
        g_off[i] = excl;
        g_cursor[i] = excl;
    }
}

__global__ void fill_kernel(const float* __restrict__ ew, int E) {
    int e = blockIdx.x * blockDim.x + threadIdx.x;
    if (e >= E) return;
    int d = g_dst[e];
    int pos = atomicAdd(&g_cursor[d], 1);
    g_csr[pos] = make_int2(g_src[e], __float_as_int(ew[e]));
}

// ---------------------------------------------------------------------------
// GEMM1 (tensor cores, 3-term bf16 split):  support1h = fp16(X @ W1)
// (R9/R13-proven: pre-split planes, cp.async double-buffer, ldmatrix)
// ---------------------------------------------------------------------------
__device__ __forceinline__ void mma16816(float* c, const unsigned* a, const unsigned* b) {
    asm volatile(
        "mma.sync.aligned.m16n8k16.row.col.f32.bf16.bf16.f32 "
        "{%0,%1,%2,%3}, {%4,%5,%6,%7}, {%8,%9}, {%0,%1,%2,%3};\n"
        : "+f"(c[0]), "+f"(c[1]), "+f"(c[2]), "+f"(c[3])
        : "r"(a[0]), "r"(a[1]), "r"(a[2]), "r"(a[3]), "r"(b[0]), "r"(b[1]));
}

__device__ __forceinline__ void ldm_x4(unsigned* r, unsigned addr) {
    asm volatile("ldmatrix.sync.aligned.m8n8.x4.shared.b16 {%0,%1,%2,%3}, [%4];\n"
        : "=r"(r[0]), "=r"(r[1]), "=r"(r[2]), "=r"(r[3]) : "r"(addr));
}

__device__ __forceinline__ void cp16(unsigned dst, const void* src, bool pred) {
    int bytes = pred ? 16 : 0;
    asm volatile("cp.async.cg.shared.global [%0], [%1], 16, %2;\n"
                 :: "r"(dst), "l"(src), "r"(bytes));
}

__device__ __forceinline__ unsigned h2_bits(__half2 v) {
    return *(unsigned*)&v;
}

// smem tile: 128 rows x 64B (32 bf16 k).  chunk' = chunk ^ ((row>>1)&3).
__device__ __forceinline__ unsigned sw_off(int row, int chunk) {
    return (unsigned)(row * 64 + ((chunk ^ ((row >> 1) & 3)) << 4));
}

#define G1_BUF 32768   // 4 arrays x 8KB

__global__ __launch_bounds__(256, 2) void gemm1_kernel(int M)
{
    __shared__ __align__(128) unsigned char smem[2 * G1_BUF];

    const int tid = threadIdx.x;
    const int lane = tid & 31;
    const int wid = tid >> 5;
    const int g = lane >> 2;
    const int tq = lane & 3;
    const int wm = wid >> 1;
    const int wn = wid & 1;
    const int blockRow = blockIdx.x * 128;

    const unsigned sbase = (unsigned)__cvta_generic_to_shared(smem);

    float acc[2][8][4];
#pragma unroll
    for (int i = 0; i < 2; i++)
#pragma unroll
        for (int j = 0; j < 8; j++)
#pragma unroll
            for (int c = 0; c < 4; c++) acc[i][j][c] = 0.f;

#define G1_ISSUE(buf, k0)                                                     \
    {                                                                         \
        _Pragma("unroll")                                                     \
        for (int it = 0; it < 2; it++) {                                      \
            int lin = tid + it * 256;                                         \
            int row = lin >> 2;                                               \
            int ch = lin & 3;                                                 \
            unsigned so = sw_off(row, ch);                                    \
            int gr = blockRow + row;                                          \
            bool av = gr < M;                                                 \
            int grc = av ? gr : 0;                                            \
            unsigned b0 = sbase + (buf) * G1_BUF;                             \
            cp16(b0 + so,         g_xhi   + (size_t)grc * FIN + (k0) + ch * 8, av);   \
            cp16(b0 + 8192 + so,  g_xlo   + (size_t)grc * FIN + (k0) + ch * 8, av);   \
            cp16(b0 + 16384 + so, g_w1thi + (size_t)row * FIN + (k0) + ch * 8, true); \
            cp16(b0 + 24576 + so, g_w1tlo + (size_t)row * FIN + (k0) + ch * 8, true); \
        }                                                                     \
        asm volatile("cp.async.commit_group;\n");                             \
    }

    G1_ISSUE(0, 0);

    const int mat = lane >> 3;
    const int r8 = lane & 7;

    for (int itk = 0; itk < FIN / 32; itk++) {
        if (itk + 1 < FIN / 32) {
            G1_ISSUE((itk + 1) & 1, (itk + 1) * 32);
            asm volatile("cp.async.wait_group 1;\n");
        } else {
            asm volatile("cp.async.wait_group 0;\n");
        }
        __syncthreads();

        const unsigned Ah = sbase + (itk & 1) * G1_BUF;
        const unsigned Al = Ah + 8192;
        const unsigned Bh = Ah + 16384;
        const unsigned Bl = Ah + 24576;

#pragma unroll
        for (int kk = 0; kk < 2; kk++) {
            unsigned afh[2][4], afl[2][4];
#pragma unroll
            for (int i = 0; i < 2; i++) {
                int row = wm * 32 + i * 16 + (mat & 1) * 8 + r8;
                int ch = kk * 2 + (mat >> 1);
                unsigned a = sw_off(row, ch);
                ldm_x4(afh[i], Ah + a);
                ldm_x4(afl[i], Al + a);
            }
#pragma unroll
            for (int p = 0; p < 4; p++) {
                int nrow = wn * 64 + p * 16 + (mat & 1) * 8 + r8;
                int ch = kk * 2 + (mat >> 1);
                unsigned bo = sw_off(nrow, ch);
                unsigned bh[4], bl[4];
                ldm_x4(bh, Bh + bo);
                ldm_x4(bl, Bl + bo);
                unsigned bhe[2] = {bh[0], bh[2]}, bho[2] = {bh[1], bh[3]};
                unsigned ble[2] = {bl[0], bl[2]}, blo2[2] = {bl[1], bl[3]};
#pragma unroll
                for (int i = 0; i < 2; i++) {
                    mma16816(acc[i][2 * p],     afh[i], bhe);
                    mma16816(acc[i][2 * p],     afh[i], ble);
                    mma16816(acc[i][2 * p],     afl[i], bhe);
                    mma16816(acc[i][2 * p + 1], afh[i], bho);
                    mma16816(acc[i][2 * p + 1], afh[i], blo2);
                    mma16816(acc[i][2 * p + 1], afl[i], bho);
                }
            }
        }
        __syncthreads();
    }

    // epilogue: fp16 store (half2 per col-pair)
#pragma unroll
    for (int i = 0; i < 2; i++) {
        int r0 = blockRow + wm * 32 + i * 16 + g;
        int r1 = r0 + 8;
#pragma unroll
        for (int j = 0; j < 8; j++) {
            int c = wn * 64 + j * 8 + 2 * tq;
            if (r0 < M)
                *(__half2*)(g_support1h + (size_t)r0 * FHID + c) =
                    __floats2half2_rn(acc[i][j][0], acc[i][j][1]);
            if (r1 < M)
                *(__half2*)(g_support1h + (size_t)r1 * FHID + c) =
                    __floats2half2_rn(acc[i][j][2], acc[i][j][3]);
        }
    }
}

// ---------------------------------------------------------------------------
// Agg1 (CSR, fp16 gather): FOUR warps per node, 32 feats (64 B) per warp.
// 400K warps in flight; per-warp MLP stays 2 (no front-batch contention).
// ---------------------------------------------------------------------------
__global__ __launch_bounds__(256) void agg1_kernel(int M)
{
    size_t gid = (size_t)blockIdx.x * blockDim.x + threadIdx.x;
    int node = (int)(gid >> 7);          // 128 threads (4 warps) per node
    int q = (int)((gid >> 5) & 3);       // which 32-feature quarter
    int lane = threadIdx.x & 31;
    if (node >= M) return;

    int beg = g_off[node];
    int end = g_off[node + 1];

    const __half* base = g_support1h + q * 32 + lane;

    float acc = 0.f;
    int i = beg;
    for (; i + 1 < end; i += 2) {
        int2 e0 = g_csr[i];
        int2 e1 = g_csr[i + 1];
        float v0 = __half2float(base[(size_t)e0.x * FHID]);
        float v1 = __half2float(base[(size_t)e1.x * FHID]);
        acc = fmaf(__int_as_float(e0.y), v0, acc);
        acc = fmaf(__int_as_float(e1.y), v1, acc);
    }
    if (i < end) {
        int2 e0 = g_csr[i];
        float v0 = __half2float(base[(size_t)e0.x * FHID]);
        acc = fmaf(__int_as_float(e0.y), v0, acc);
    }
    g_agg1h[(size_t)node * FHID + q * 32 + lane] = __float2half_rn(acc);
}

// ---------------------------------------------------------------------------
// GEMM2 (fused bias+relu, fp16 in, register-tiled 1x5, fp16 out):
//   support2h = fp16( relu(agg1h+b1) @ W2[128,40] )
// ---------------------------------------------------------------------------
#define XS_PITCH 132   // 128 + 4 pad: kills r*128 same-bank conflicts

__global__ __launch_bounds__(256) void gemm2_kernel(
    const float* __restrict__ W2, const float* __restrict__ b1, int M)
{
    __shared__ float Ws[FHID * FOUT];        // 20 KB
    __shared__ float Xs[32 * XS_PITCH];      // 16.5 KB

    const int tid = threadIdx.x;
    const int row0 = blockIdx.x * 32;

    for (int i = tid; i < FHID * FOUT; i += 256) Ws[i] = W2[i];

    for (int i = tid; i < 1024; i += 256) {
        int r = i >> 5;
        int c4 = (i & 31) * 4;
        int gr = row0 + r;
        float4 v = make_float4(0.f, 0.f, 0.f, 0.f);
        if (gr < M) {
            uint2 u = *(const uint2*)(g_agg1h + (size_t)gr * FHID + c4);
            float2 a = __half22float2(*(__half2*)&u.x);
            float2 b = __half22float2(*(__half2*)&u.y);
            v.x = fmaxf(a.x + b1[c4 + 0], 0.f);
            v.y = fmaxf(a.y + b1[c4 + 1], 0.f);
            v.z = fmaxf(b.x + b1[c4 + 2], 0.f);
            v.w = fmaxf(b.y + b1[c4 + 3], 0.f);
        }
        *(float4*)&Xs[r * XS_PITCH + c4] = v;
    }
    __syncthreads();

    {
        int r = tid >> 3;          // 0..31
        int t = tid & 7;           // 0..7 -> cols t*5..t*5+4
        float acc[5] = {0.f, 0.f, 0.f, 0.f, 0.f};
        const float* xr = &Xs[r * XS_PITCH];
#pragma unroll 4
        for (int k = 0; k < FHID; k++) {
            float xv = xr[k];
            const float* wr = &Ws[k * FOUT + t * 5];
#pragma unroll
            for (int q = 0; q < 5; q++) acc[q] = fmaf(xv, wr[q], acc[q]);
        }
        int gr = row0 + r;
        if (gr < M) {
            __half* op = g_support2h + (size_t)gr * FOUT + t * 5;
#pragma unroll
            for (int q = 0; q < 5; q++) op[q] = __float2half_rn(acc[q]);
        }
    }
}

// ---------------------------------------------------------------------------
// Agg2 + bias + log_softmax fused. 8 threads/node, 5 feats each.
// fp16 support2 gather; CSR batched 8-wide via GROUP-masked width-8 shuffles.
// ---------------------------------------------------------------------------
__global__ __launch_bounds__(256) void agg2_lsm_kernel(
    const float* __restrict__ b2, float* __restrict__ out, int M)
{
    size_t gid = (size_t)blockIdx.x * blockDim.x + threadIdx.x;
    int node = (int)(gid >> 3);
    int t = (int)(gid & 7);
    if (node >= M) return;

    const int lane = threadIdx.x & 31;
    const unsigned gmask = 0xFFu << (lane & 24);   // this 8-lane group only

    int beg = g_off[node];
    int end = g_off[node + 1];

    float acc[5] = {0.f, 0.f, 0.f, 0.f, 0.f};
    for (int base = beg; base < end; base += 8) {
        int idx = base + t;
        int2 ed = make_int2(0, 0);           // w=0 -> no-op contribution
        if (idx < end) ed = g_csr[idx];
        int nleft = min(8, end - base);      // uniform across the group
#pragma unroll 8
        for (int j = 0; j < 8; j++) {
            if (j >= nleft) break;
            int   s = __shfl_sync(gmask, ed.x, j, 8);
            float w = __int_as_float(__shfl_sync(gmask, ed.y, j, 8));
            const __half* row = g_support2h + (size_t)s * FOUT + t * 5;
#pragma unroll
            for (int q = 0; q < 5; q++)
                acc[q] = fmaf(w, __half2float(row[q]), acc[q]);
        }
    }
#pragma unroll
    for (int j = 0; j < 5; j++) acc[j] += b2[t * 5 + j];

    float m = acc[0];
#pragma unroll
    for (int j = 1; j < 5; j++) m = fmaxf(m, acc[j]);
#pragma unroll
    for (int off = 1; off < 8; off <<= 1)
        m = fmaxf(m, __shfl_xor_sync(gmask, m, off, 8));

    float ssum = 0.f;
#pragma unroll
    for (int j = 0; j < 5; j++) ssum += __expf(acc[j] - m);
#pragma unroll
    for (int off = 1; off < 8; off <<= 1)
        ssum += __shfl_xor_sync(gmask, ssum, off, 8);

    float l = m + __logf(ssum);
    float* op = out + (size_t)node * FOUT + t * 5;
#pragma unroll
    for (int j = 0; j < 5; j++) op[j] = acc[j] - l;
}

// ---------------------------------------------------------------------------
// Launch — fork/join (R9 structure); gemm1 at issue index 3 (profiled slot).
// ---------------------------------------------------------------------------
extern "C" void kernel_launch(void* const* d_in, const int* in_sizes, int n_in,
                              void* d_out, int out_size)
{
    const float* x   = (const float*)d_in[0];
    const void*  ei  = d_in[1];
    const float* ew  = (const float*)d_in[2];
    const float* W1  = (const float*)d_in[3];
    const float* b1  = (const float*)d_in[4];
    const float* W2  = (const float*)d_in[5];
    const float* b2  = (const float*)d_in[6];
    float* out = (float*)d_out;

    const int M = in_sizes[0] / FIN;     // 100000
    const int E = in_sizes[2];           // 3200000
    const int nb = (M + SB - 1) / SB;

    static cudaStream_t s2 = nullptr;
    static cudaEvent_t evFork = nullptr, evJoin = nullptr;
    if (s2 == nullptr) {
        cudaStreamCreateWithFlags(&s2, cudaStreamNonBlocking);
        cudaEventCreateWithFlags(&evFork, cudaEventDisableTiming);
        cudaEventCreateWithFlags(&evJoin, cudaEventDisableTiming);
    }

    // main stream: detect, then fork
    detect_kernel<<<1, 256>>>(ei, E, M);                                   // 0
    cudaEventRecord(evFork, 0);
    cudaStreamWaitEvent(s2, evFork, 0);

    // main stream chain A: split + gemm1  (gemm1 = 4th kernel launch issued)
    split_w1_kernel<<<(FIN * FHID + 255) / 256, 256>>>(W1);                // 1
    {
        size_t n4 = (size_t)M * (FIN / 4);
        split_x_kernel<<<(unsigned)((n4 + 255) / 256), 256>>>(x, M);       // 2
    }
    gemm1_kernel<<<(M + 127) / 128, 256>>>(M);                             // 3 <- profiled

    // side stream chain B: CSR build
    zero_deg_kernel<<<(M + 255) / 256, 256, 0, s2>>>(M);
    decode_hist_kernel<<<(E + 255) / 256, 256, 0, s2>>>(ei, E, M);
    scan1_kernel<<<nb, SB, 0, s2>>>(M);
    scan2_kernel<<<1, MAXSB, 0, s2>>>(nb, E, M);
    scan3_kernel<<<nb, SB, 0, s2>>>(M);
    fill_kernel<<<(E + 255) / 256, 256, 0, s2>>>(ew, E);
    cudaEventRecord(evJoin, s2);

    // join, then the dependent tail on the main stream
    cudaStreamWaitEvent(0, evJoin, 0);
    {
        size_t threads = (size_t)M * 128;   // 4 warps per node
        agg1_kernel<<<(unsigned)((threads + 255) / 256), 256>>>(M);
    }
    gemm2_kernel<<<(M + 31) / 32, 256>>>(W2, b1, M);
    {
        size_t threads = (size_t)M * 8;
        agg2_lsm_kernel<<<(unsigned)((threads + 255) / 256), 256>>>(b2, out, M);
    }
}

// round 17
// speedup vs baseline: 1.2763x; 1.2763x over previous
#include <cuda_runtime.h>
#include <cuda_bf16.h>
#include <cuda_fp16.h>

// Problem constants (fixed by the dataset)
#define NNODES   100000
#define FIN      512
#define FHID     128
#define FOUT     40
#define NEDGES   3200000

#define SB 256           // scan block size
#define MAXSB 1024       // max scan blocks

// Scratch (device globals; no runtime allocation allowed)
__device__ __align__(256) __half g_support1h[(size_t)NNODES * FHID];  // fp16 gather table
__device__ __align__(256) __half g_agg1h[(size_t)NNODES * FHID];      // fp16 agg1
__device__ __align__(256) float g_support2[(size_t)NNODES * FOUT];
__device__ __align__(256) __nv_bfloat16 g_xhi[(size_t)NNODES * FIN];
__device__ __align__(256) __nv_bfloat16 g_xlo[(size_t)NNODES * FIN];
__device__ __align__(256) __nv_bfloat16 g_w1thi[FHID * FIN];   // transposed [n][k]
__device__ __align__(256) __nv_bfloat16 g_w1tlo[FHID * FIN];
__device__ __align__(256) int   g_src[NEDGES];
__device__ __align__(256) int   g_dst[NEDGES];
__device__ __align__(256) int   g_deg[NNODES];
__device__ __align__(256) int   g_off[NNODES + 1];
__device__ __align__(256) int   g_cursor[NNODES];
__device__ __align__(256) int2  g_csr[NEDGES];       // {src, w_bits}
__device__ __align__(256) int   g_bsum[MAXSB];
__device__ __align__(256) int   g_bbase[MAXSB];
__device__ int g_is64;

// ---------------------------------------------------------------------------
// Edge-index dtype detection (int64 vs int32), parallel
// ---------------------------------------------------------------------------
__global__ void detect_kernel(const void* ei, int E, int M) {
    const long long* p64 = (const long long*)ei;
    int step = E / 4096;
    int bad = 0;
#pragma unroll
    for (int j = 0; j < 16; j++) {
        int k = threadIdx.x * 16 + j;
        long long v = p64[(long long)k * step];
        if (v < 0 || v >= M) bad = 1;
    }
    bad = __syncthreads_or(bad);
    if (threadIdx.x == 0) g_is64 = !bad;
}

// ---------------------------------------------------------------------------
// Split precompute: x -> hi/lo bf16 planes (row-chunked); W1 -> transposed
// ---------------------------------------------------------------------------
__global__ void split_x_kernel(const float* __restrict__ x, int rowBase, int rowEnd) {
    size_t base4 = (size_t)rowBase * (FIN / 4);
    size_t i = base4 + (size_t)blockIdx.x * blockDim.x + threadIdx.x;   // float4 idx
    size_t end4 = (size_t)rowEnd * (FIN / 4);
    if (i >= end4) return;
    float4 v = ((const float4*)x)[i];
    __nv_bfloat16 h0 = __float2bfloat16_rn(v.x);
    __nv_bfloat16 h1 = __float2bfloat16_rn(v.y);
    __nv_bfloat16 h2 = __float2bfloat16_rn(v.z);
    __nv_bfloat16 h3 = __float2bfloat16_rn(v.w);
    __nv_bfloat16 l0 = __float2bfloat16_rn(v.x - __bfloat162float(h0));
    __nv_bfloat16 l1 = __float2bfloat16_rn(v.y - __bfloat162float(h1));
    __nv_bfloat16 l2 = __float2bfloat16_rn(v.z - __bfloat162float(h2));
    __nv_bfloat16 l3 = __float2bfloat16_rn(v.w - __bfloat162float(h3));
    __nv_bfloat162 hp0; hp0.x = h0; hp0.y = h1;
    __nv_bfloat162 hp1; hp1.x = h2; hp1.y = h3;
    __nv_bfloat162 lp0; lp0.x = l0; lp0.y = l1;
    __nv_bfloat162 lp1; lp1.x = l2; lp1.y = l3;
    uint2 hv = make_uint2(*(unsigned*)&hp0, *(unsigned*)&hp1);
    uint2 lv = make_uint2(*(unsigned*)&lp0, *(unsigned*)&lp1);
    ((uint2*)g_xhi)[i] = hv;
    ((uint2*)g_xlo)[i] = lv;
}

__global__ void split_w1_kernel(const float* __restrict__ W1) {
    int i = blockIdx.x * blockDim.x + threadIdx.x;    // k*FHID + n
    if (i >= FIN * FHID) return;
    int k = i / FHID;
    int n = i % FHID;
    float v = W1[i];
    __nv_bfloat16 h = __float2bfloat16_rn(v);
    __nv_bfloat16 l = __float2bfloat16_rn(v - __bfloat162float(h));
    g_w1thi[n * FIN + k] = h;
    g_w1tlo[n * FIN + k] = l;
}

__global__ void zero_deg_kernel(int M) {
    int i = blockIdx.x * blockDim.x + threadIdx.x;
    if (i < M) g_deg[i] = 0;
}

__global__ void decode_hist_kernel(const void* ei, int E, int M) {
    int e = blockIdx.x * blockDim.x + threadIdx.x;
    if (e >= E) return;
    int s, d;
    if (g_is64) {
        const long long* p = (const long long*)ei;
        s = (int)p[e];
        d = (int)p[(size_t)E + e];
    } else {
        const int* p = (const int*)ei;
        s = p[e];
        d = p[(size_t)E + e];
    }
    s = min(max(s, 0), M - 1);
    d = min(max(d, 0), M - 1);
    g_src[e] = s;
    g_dst[e] = d;
    atomicAdd(&g_deg[d], 1);
}

// ---- 3-phase multi-block exclusive scan ----------------------------------
__global__ void scan1_kernel(int M) {
    __shared__ int sh[SB];
    int t = threadIdx.x;
    int i = blockIdx.x * SB + t;
    sh[t] = (i < M) ? g_deg[i] : 0;
    __syncthreads();
#pragma unroll
    for (int o = SB / 2; o > 0; o >>= 1) {
        if (t < o) sh[t] += sh[t + o];
        __syncthreads();
    }
    if (t == 0) g_bsum[blockIdx.x] = sh[0];
}

__global__ __launch_bounds__(MAXSB) void scan2_kernel(int nb, int E, int M) {
    __shared__ int sh[MAXSB];
    int t = threadIdx.x;
    sh[t] = (t < nb) ? g_bsum[t] : 0;
    __syncthreads();
#pragma unroll
    for (int o = 1; o < MAXSB; o <<= 1) {
        int u = (t >= o) ? sh[t - o] : 0;
        __syncthreads();
        sh[t] += u;
        __syncthreads();
    }
    if (t < nb) g_bbase[t] = (t > 0) ? sh[t - 1] : 0;
    if (t == 0) g_off[M] = E;
}

__global__ void scan3_kernel(int M) {
    __shared__ int sh[SB];
    int t = threadIdx.x;
    int i = blockIdx.x * SB + t;
    int v = (i < M) ? g_deg[i] : 0;
    sh[t] = v;
    __syncthreads();
#pragma unroll
    for (int o = 1; o < SB; o <<= 1) {
        int u = (t >= o) ? sh[t - o] : 0;
        __syncthreads();
        sh[t] += u;
        __syncthreads();
    }
    if (i < M) {
        int excl = sh[t] - v + g_bbase[blockIdx.x];
        g_off[i] = excl;
        g_cursor[i] = excl;
    }
}

__global__ void fill_kernel(const float* __restrict__ ew, int E) {
    int e = blockIdx.x * blockDim.x + threadIdx.x;
    if (e >= E) return;
    int d = g_dst[e];
    int pos = atomicAdd(&g_cursor[d], 1);
    g_csr[pos] = make_int2(g_src[e], __float_as_int(ew[e]));
}

// ---------------------------------------------------------------------------
// GEMM1 (tensor cores, 3-term bf16 split):  support1h = fp16(X @ W1)
// Row-chunked: processes rows [rowBase, rowEnd).
// ---------------------------------------------------------------------------
__device__ __forceinline__ void mma16816(float* c, const unsigned* a, const unsigned* b) {
    asm volatile(
        "mma.sync.aligned.m16n8k16.row.col.f32.bf16.bf16.f32 "
        "{%0,%1,%2,%3}, {%4,%5,%6,%7}, {%8,%9}, {%0,%1,%2,%3};\n"
        : "+f"(c[0]), "+f"(c[1]), "+f"(c[2]), "+f"(c[3])
        : "r"(a[0]), "r"(a[1]), "r"(a[2]), "r"(a[3]), "r"(b[0]), "r"(b[1]));
}

__device__ __forceinline__ void ldm_x4(unsigned* r, unsigned addr) {
    asm volatile("ldmatrix.sync.aligned.m8n8.x4.shared.b16 {%0,%1,%2,%3}, [%4];\n"
        : "=r"(r[0]), "=r"(r[1]), "=r"(r[2]), "=r"(r[3]) : "r"(addr));
}

__device__ __forceinline__ void cp16(unsigned dst, const void* src, bool pred) {
    int bytes = pred ? 16 : 0;
    asm volatile("cp.async.cg.shared.global [%0], [%1], 16, %2;\n"
                 :: "r"(dst), "l"(src), "r"(bytes));
}

__device__ __forceinline__ unsigned h2_bits(__half2 v) {
    return *(unsigned*)&v;
}

// smem tile: 128 rows x 64B (32 bf16 k).  chunk' = chunk ^ ((row>>1)&3).
__device__ __forceinline__ unsigned sw_off(int row, int chunk) {
    return (unsigned)(row * 64 + ((chunk ^ ((row >> 1) & 3)) << 4));
}

#define G1_BUF 32768   // 4 arrays x 8KB

__global__ __launch_bounds__(256, 2) void gemm1_kernel(int rowBase, int rowEnd)
{
    __shared__ __align__(128) unsigned char smem[2 * G1_BUF];

    const int tid = threadIdx.x;
    const int lane = tid & 31;
    const int wid = tid >> 5;
    const int g = lane >> 2;
    const int tq = lane & 3;
    const int wm = wid >> 1;
    const int wn = wid & 1;
    const int blockRow = rowBase + blockIdx.x * 128;

    const unsigned sbase = (unsigned)__cvta_generic_to_shared(smem);

    float acc[2][8][4];
#pragma unroll
    for (int i = 0; i < 2; i++)
#pragma unroll
        for (int j = 0; j < 8; j++)
#pragma unroll
            for (int c = 0; c < 4; c++) acc[i][j][c] = 0.f;

#define G1_ISSUE(buf, k0)                                                     \
    {                                                                         \
        _Pragma("unroll")                                                     \
        for (int it = 0; it < 2; it++) {                                      \
            int lin = tid + it * 256;                                         \
            int row = lin >> 2;                                               \
            int ch = lin & 3;                                                 \
            unsigned so = sw_off(row, ch);                                    \
            int gr = blockRow + row;                                          \
            bool av = gr < rowEnd;                                            \
            int grc = av ? gr : 0;                                            \
            unsigned b0 = sbase + (buf) * G1_BUF;                             \
            cp16(b0 + so,         g_xhi   + (size_t)grc * FIN + (k0) + ch * 8, av);   \
            cp16(b0 + 8192 + so,  g_xlo   + (size_t)grc * FIN + (k0) + ch * 8, av);   \
            cp16(b0 + 16384 + so, g_w1thi + (size_t)row * FIN + (k0) + ch * 8, true); \
            cp16(b0 + 24576 + so, g_w1tlo + (size_t)row * FIN + (k0) + ch * 8, true); \
        }                                                                     \
        asm volatile("cp.async.commit_group;\n");                             \
    }

    G1_ISSUE(0, 0);

    const int mat = lane >> 3;
    const int r8 = lane & 7;

    for (int itk = 0; itk < FIN / 32; itk++) {
        if (itk + 1 < FIN / 32) {
            G1_ISSUE((itk + 1) & 1, (itk + 1) * 32);
            asm volatile("cp.async.wait_group 1;\n");
        } else {
            asm volatile("cp.async.wait_group 0;\n");
        }
        __syncthreads();

        const unsigned Ah = sbase + (itk & 1) * G1_BUF;
        const unsigned Al = Ah + 8192;
        const unsigned Bh = Ah + 16384;
        const unsigned Bl = Ah + 24576;

#pragma unroll
        for (int kk = 0; kk < 2; kk++) {
            unsigned afh[2][4], afl[2][4];
#pragma unroll
            for (int i = 0; i < 2; i++) {
                int row = wm * 32 + i * 16 + (mat & 1) * 8 + r8;
                int ch = kk * 2 + (mat >> 1);
                unsigned a = sw_off(row, ch);
                ldm_x4(afh[i], Ah + a);
                ldm_x4(afl[i], Al + a);
            }
#pragma unroll
            for (int p = 0; p < 4; p++) {
                int nrow = wn * 64 + p * 16 + (mat & 1) * 8 + r8;
                int ch = kk * 2 + (mat >> 1);
                unsigned bo = sw_off(nrow, ch);
                unsigned bh[4], bl[4];
                ldm_x4(bh, Bh + bo);
                ldm_x4(bl, Bl + bo);
                unsigned bhe[2] = {bh[0], bh[2]}, bho[2] = {bh[1], bh[3]};
                unsigned ble[2] = {bl[0], bl[2]}, blo2[2] = {bl[1], bl[3]};
#pragma unroll
                for (int i = 0; i < 2; i++) {
                    mma16816(acc[i][2 * p],     afh[i], bhe);
                    mma16816(acc[i][2 * p],     afh[i], ble);
                    mma16816(acc[i][2 * p],     afl[i], bhe);
                    mma16816(acc[i][2 * p + 1], afh[i], bho);
                    mma16816(acc[i][2 * p + 1], afh[i], blo2);
                    mma16816(acc[i][2 * p + 1], afl[i], bho);
                }
            }
        }
        __syncthreads();
    }

    // epilogue: fp16 store (half2 per col-pair)
#pragma unroll
    for (int i = 0; i < 2; i++) {
        int r0 = blockRow + wm * 32 + i * 16 + g;
        int r1 = r0 + 8;
#pragma unroll
        for (int j = 0; j < 8; j++) {
            int c = wn * 64 + j * 8 + 2 * tq;
            if (r0 < rowEnd)
                *(__half2*)(g_support1h + (size_t)r0 * FHID + c) =
                    __floats2half2_rn(acc[i][j][0], acc[i][j][1]);
            if (r1 < rowEnd)
                *(__half2*)(g_support1h + (size_t)r1 * FHID + c) =
                    __floats2half2_rn(acc[i][j][2], acc[i][j][3]);
        }
    }
}

// ---------------------------------------------------------------------------
// Agg1 (CSR, fp16 gather): TWO warps per node, 64 feats (128 B = 1 line) each.
// (R14-proven configuration.)
// ---------------------------------------------------------------------------
__global__ __launch_bounds__(256) void agg1_kernel(int M)
{
    size_t gid = (size_t)blockIdx.x * blockDim.x + threadIdx.x;
    int node = (int)(gid >> 6);          // 64 threads (2 warps) per node
    int half = (int)((gid >> 5) & 1);    // which 64-feature half
    int lane = threadIdx.x & 31;
    if (node >= M) return;

    int beg = g_off[node];
    int end = g_off[node + 1];

    const __half* base = g_support1h + half * 64;

    float2 acc = make_float2(0.f, 0.f);
    int i = beg;
    for (; i + 1 < end; i += 2) {
        int2 e0 = g_csr[i];
        int2 e1 = g_csr[i + 1];
        unsigned u0 = ((const unsigned*)(base + (size_t)e0.x * FHID))[lane];
        unsigned u1 = ((const unsigned*)(base + (size_t)e1.x * FHID))[lane];
        float2 a0 = __half22float2(*(__half2*)&u0);
        float2 a1 = __half22float2(*(__half2*)&u1);
        float w0 = __int_as_float(e0.y);
        float w1 = __int_as_float(e1.y);
        acc.x = fmaf(w0, a0.x, acc.x); acc.y = fmaf(w0, a0.y, acc.y);
        acc.x = fmaf(w1, a1.x, acc.x); acc.y = fmaf(w1, a1.y, acc.y);
    }
    if (i < end) {
        int2 e0 = g_csr[i];
        unsigned u0 = ((const unsigned*)(base + (size_t)e0.x * FHID))[lane];
        float2 a0 = __half22float2(*(__half2*)&u0);
        float w0 = __int_as_float(e0.y);
        acc.x = fmaf(w0, a0.x, acc.x); acc.y = fmaf(w0, a0.y, acc.y);
    }
    ((unsigned*)(g_agg1h + (size_t)node * FHID + half * 64))[lane] =
        h2_bits(__floats2half2_rn(acc.x, acc.y));
}

// ---------------------------------------------------------------------------
// GEMM2 (fused bias+relu, fp16 in, register-tiled 1x5, fp32 out — R14-proven)
// ---------------------------------------------------------------------------
#define XS_PITCH 132   // 128 + 4 pad: kills r*128 same-bank conflicts

__global__ __launch_bounds__(256) void gemm2_kernel(
    const float* __restrict__ W2, const float* __restrict__ b1, int M)
{
    __shared__ float Ws[FHID * FOUT];        // 20 KB
    __shared__ float Xs[32 * XS_PITCH];      // 16.5 KB

    const int tid = threadIdx.x;
    const int row0 = blockIdx.x * 32;

    for (int i = tid; i < FHID * FOUT; i += 256) Ws[i] = W2[i];

    for (int i = tid; i < 1024; i += 256) {
        int r = i >> 5;
        int c4 = (i & 31) * 4;
        int gr = row0 + r;
        float4 v = make_float4(0.f, 0.f, 0.f, 0.f);
        if (gr < M) {
            uint2 u = *(const uint2*)(g_agg1h + (size_t)gr * FHID + c4);
            float2 a = __half22float2(*(__half2*)&u.x);
            float2 b = __half22float2(*(__half2*)&u.y);
            v.x = fmaxf(a.x + b1[c4 + 0], 0.f);
            v.y = fmaxf(a.y + b1[c4 + 1], 0.f);
            v.z = fmaxf(b.x + b1[c4 + 2], 0.f);
            v.w = fmaxf(b.y + b1[c4 + 3], 0.f);
        }
        *(float4*)&Xs[r * XS_PITCH + c4] = v;
    }
    __syncthreads();

    {
        int r = tid >> 3;          // 0..31
        int t = tid & 7;           // 0..7 -> cols t*5..t*5+4
        float acc[5] = {0.f, 0.f, 0.f, 0.f, 0.f};
        const float* xr = &Xs[r * XS_PITCH];
#pragma unroll 4
        for (int k = 0; k < FHID; k++) {
            float xv = xr[k];
            const float* wr = &Ws[k * FOUT + t * 5];
#pragma unroll
            for (int q = 0; q < 5; q++) acc[q] = fmaf(xv, wr[q], acc[q]);
        }
        int gr = row0 + r;
        if (gr < M) {
            float* op = g_support2 + (size_t)gr * FOUT + t * 5;
#pragma unroll
            for (int q = 0; q < 5; q++) op[q] = acc[q];
        }
    }
}

// ---------------------------------------------------------------------------
// Agg2 + bias + log_softmax fused. 8 threads/node, 5 feats each. (R14-proven)
// ---------------------------------------------------------------------------
__global__ __launch_bounds__(256) void agg2_lsm_kernel(
    const float* __restrict__ b2, float* __restrict__ out, int M)
{
    size_t gid = (size_t)blockIdx.x * blockDim.x + threadIdx.x;
    int node = (int)(gid >> 3);
    int t = (int)(gid & 7);
    if (node >= M) return;

    const int lane = threadIdx.x & 31;
    const unsigned gmask = 0xFFu << (lane & 24);   // this 8-lane group only

    int beg = g_off[node];
    int end = g_off[node + 1];

    float acc[5] = {0.f, 0.f, 0.f, 0.f, 0.f};
    for (int base = beg; base < end; base += 8) {
        int idx = base + t;
        int2 ed = make_int2(0, 0);           // w=0 -> no-op contribution
        if (idx < end) ed = g_csr[idx];
        int nleft = min(8, end - base);      // uniform across the group
#pragma unroll 8
        for (int j = 0; j < 8; j++) {
            if (j >= nleft) break;
            int   s = __shfl_sync(gmask, ed.x, j, 8);
            float w = __int_as_float(__shfl_sync(gmask, ed.y, j, 8));
            const float* row = g_support2 + (size_t)s * FOUT + t * 5;
#pragma unroll
            for (int q = 0; q < 5; q++) acc[q] = fmaf(w, row[q], acc[q]);
        }
    }
#pragma unroll
    for (int j = 0; j < 5; j++) acc[j] += b2[t * 5 + j];

    float m = acc[0];
#pragma unroll
    for (int j = 1; j < 5; j++) m = fmaxf(m, acc[j]);
#pragma unroll
    for (int off = 1; off < 8; off <<= 1)
        m = fmaxf(m, __shfl_xor_sync(gmask, m, off, 8));

    float ssum = 0.f;
#pragma unroll
    for (int j = 0; j < 5; j++) ssum += __expf(acc[j] - m);
#pragma unroll
    for (int off = 1; off < 8; off <<= 1)
        ssum += __shfl_xor_sync(gmask, ssum, off, 8);

    float l = m + __logf(ssum);
    float* op = out + (size_t)node * FOUT + t * 5;
#pragma unroll
    for (int j = 0; j < 5; j++) op[j] = acc[j] - l;
}

// ---------------------------------------------------------------------------
// Launch — fork/join + chunked split_x/gemm1 pipeline (2 chunks, stream s3).
// ---------------------------------------------------------------------------
extern "C" void kernel_launch(void* const* d_in, const int* in_sizes, int n_in,
                              void* d_out, int out_size)
{
    const float* x   = (const float*)d_in[0];
    const void*  ei  = d_in[1];
    const float* ew  = (const float*)d_in[2];
    const float* W1  = (const float*)d_in[3];
    const float* b1  = (const float*)d_in[4];
    const float* W2  = (const float*)d_in[5];
    const float* b2  = (const float*)d_in[6];
    float* out = (float*)d_out;

    const int M = in_sizes[0] / FIN;     // 100000
    const int E = in_sizes[2];           // 3200000
    const int nb = (M + SB - 1) / SB;

    // chunk boundary: multiple of 128 near M/2
    const int C0 = ((M / 2 + 127) / 128) * 128;   // 50048

    static cudaStream_t s2 = nullptr, s3 = nullptr;
    static cudaEvent_t evFork = nullptr, evJoin = nullptr;
    static cudaEvent_t evS0 = nullptr, evS1 = nullptr, evG = nullptr;
    if (s2 == nullptr) {
        cudaStreamCreateWithFlags(&s2, cudaStreamNonBlocking);
        cudaStreamCreateWithFlags(&s3, cudaStreamNonBlocking);
        cudaEventCreateWithFlags(&evFork, cudaEventDisableTiming);
        cudaEventCreateWithFlags(&evJoin, cudaEventDisableTiming);
        cudaEventCreateWithFlags(&evS0, cudaEventDisableTiming);
        cudaEventCreateWithFlags(&evS1, cudaEventDisableTiming);
        cudaEventCreateWithFlags(&evG, cudaEventDisableTiming);
    }

    // main stream: detect, then fork
    detect_kernel<<<1, 256>>>(ei, E, M);
    cudaEventRecord(evFork, 0);
    cudaStreamWaitEvent(s2, evFork, 0);
    cudaStreamWaitEvent(s3, evFork, 0);

    // main chain A: W1 split + x split chunk 0, then chunk 1
    split_w1_kernel<<<(FIN * FHID + 255) / 256, 256>>>(W1);
    {
        size_t n4 = (size_t)C0 * (FIN / 4);
        split_x_kernel<<<(unsigned)((n4 + 255) / 256), 256>>>(x, 0, C0);
    }
    cudaEventRecord(evS0, 0);

    // s3: gemm1 chunk 0 (overlaps with split_x chunk 1 on main)
    cudaStreamWaitEvent(s3, evS0, 0);
    gemm1_kernel<<<C0 / 128, 256, 0, s3>>>(0, C0);

    // main: split_x chunk 1
    {
        size_t n4 = (size_t)(M - C0) * (FIN / 4);
        split_x_kernel<<<(unsigned)((n4 + 255) / 256), 256>>>(x, C0, M);
    }
    cudaEventRecord(evS1, 0);

    // s3: gemm1 chunk 1
    cudaStreamWaitEvent(s3, evS1, 0);
    gemm1_kernel<<<(M - C0 + 127) / 128, 256, 0, s3>>>(C0, M);
    cudaEventRecord(evG, s3);

    // s2: CSR build
    zero_deg_kernel<<<(M + 255) / 256, 256, 0, s2>>>(M);
    decode_hist_kernel<<<(E + 255) / 256, 256, 0, s2>>>(ei, E, M);
    scan1_kernel<<<nb, SB, 0, s2>>>(M);
    scan2_kernel<<<1, MAXSB, 0, s2>>>(nb, E, M);
    scan3_kernel<<<nb, SB, 0, s2>>>(M);
    fill_kernel<<<(E + 255) / 256, 256, 0, s2>>>(ew, E);
    cudaEventRecord(evJoin, s2);

    // join: tail needs gemm1 (evG) + CSR (evJoin)
    cudaStreamWaitEvent(0, evJoin, 0);
    cudaStreamWaitEvent(0, evG, 0);
    {
        size_t threads = (size_t)M * 64;   // 2 warps per node
        agg1_kernel<<<(unsigned)((threads + 255) / 256), 256>>>(M);
    }
    gemm2_kernel<<<(M + 31) / 32, 256>>>(W2, b1, M);
    {
        size_t threads = (size_t)M * 8;
        agg2_lsm_kernel<<<(unsigned)((threads + 255) / 256), 256>>>(b2, out, M);
    }
}